// round 11
// baseline (speedup 1.0000x reference)
#include <cuda_runtime.h>
#include <math.h>

#define Bc 2
#define Sc 2048
#define Dc 1024
#define Hc 16
#define HDc 64
#define Rc 128
#define NBc 32
#define TOPKc 4

// ---------------- scratch (no device allocs) ----------------
__device__ float rA_q[Bc*Sc*Dc];
__device__ float rA_lat[Bc*Sc*Rc];
__device__ float rA_kv[Bc*Sc*2*Dc];
__device__ float rA_ao[Bc*Sc*Dc];
__device__ float rA_scores[Bc*NBc];
__device__ int   rA_sel[Bc*TOPKc];
__device__ float rA_vmean[Bc*Dc];
__device__ float rA_cos[Sc*32];
__device__ float rA_sin[Sc*32];

// ---------------- SGEMM NT: C[M,N] = A[M,K] * B[N,K]^T ----------------
__global__ void __launch_bounds__(256) rA_gemm(const float* __restrict__ A,
                                               const float* __restrict__ Bm,
                                               float* __restrict__ C,
                                               int M, int N, int K) {
    __shared__ float As[16][68];
    __shared__ float Bs[16][68];
    const int t  = threadIdx.x;
    const int m0 = blockIdx.y * 64;
    const int n0 = blockIdx.x * 64;
    const int ty = t >> 4, tx = t & 15;
    const int lrow = t >> 2;
    const int lcol = (t & 3) << 2;
    const float* Ag = A + (size_t)(m0 + lrow) * K + lcol;
    const float* Bg = Bm + (size_t)(n0 + lrow) * K + lcol;

    float acc[4][4];
#pragma unroll
    for (int i = 0; i < 4; i++)
#pragma unroll
        for (int j = 0; j < 4; j++) acc[i][j] = 0.f;

    for (int k0 = 0; k0 < K; k0 += 16) {
        float4 av = *(const float4*)(Ag + k0);
        float4 bv = *(const float4*)(Bg + k0);
        As[lcol+0][lrow] = av.x; As[lcol+1][lrow] = av.y;
        As[lcol+2][lrow] = av.z; As[lcol+3][lrow] = av.w;
        Bs[lcol+0][lrow] = bv.x; Bs[lcol+1][lrow] = bv.y;
        Bs[lcol+2][lrow] = bv.z; Bs[lcol+3][lrow] = bv.w;
        __syncthreads();
#pragma unroll
        for (int kk = 0; kk < 16; kk++) {
            float4 a4 = *(const float4*)&As[kk][ty << 2];
            float4 b4 = *(const float4*)&Bs[kk][tx << 2];
            float a[4] = {a4.x, a4.y, a4.z, a4.w};
            float b[4] = {b4.x, b4.y, b4.z, b4.w};
#pragma unroll
            for (int i = 0; i < 4; i++)
#pragma unroll
                for (int j = 0; j < 4; j++) acc[i][j] += a[i] * b[j];
        }
        __syncthreads();
    }
#pragma unroll
    for (int i = 0; i < 4; i++) {
        float4 v = make_float4(acc[i][0], acc[i][1], acc[i][2], acc[i][3]);
        *(float4*)(C + (size_t)(m0 + (ty << 2) + i) * N + n0 + (tx << 2)) = v;
    }
}

// ---------------- rope tables: cos/sin[s][j], theta_j = 1e5^(-2j/64) -------
__global__ void __launch_bounds__(256) rA_tables() {
    int idx = blockIdx.x * blockDim.x + threadIdx.x;
    if (idx >= Sc * 32) return;
    int s = idx >> 5;
    int j = idx & 31;
    double invf = pow(100000.0, -((double)(2 * j)) / 64.0);
    float ang = (float)s * (float)invf;
    double cd, sd;
    sincos((double)ang, &cd, &sd);
    rA_cos[idx] = (float)cd;
    rA_sin[idx] = (float)sd;
}

// ---------------- block scorer ----------------
__global__ void __launch_bounds__(256) rA_scorer(const float* __restrict__ x,
                                                 const float* __restrict__ w_scorer) {
    int bj = blockIdx.x;
    int b = bj >> 5, j = bj & 31;
    const float* base = x + (size_t)(b * Sc + j * 64) * Dc;
    float sum = 0.f;
    for (int i = threadIdx.x; i < 64 * Dc; i += 256)
        sum += base[i] * w_scorer[i & (Dc - 1)];
    __shared__ float red[256];
    red[threadIdx.x] = sum;
    __syncthreads();
    for (int off = 128; off; off >>= 1) {
        if (threadIdx.x < off) red[threadIdx.x] += red[threadIdx.x + off];
        __syncthreads();
    }
    if (threadIdx.x == 0) rA_scores[bj] = red[0] * (1.0f / 64.0f);
}

// ---------------- top-k ----------------
__global__ void rA_topk() {
    int b = threadIdx.x;
    if (b >= Bc) return;
    float sc[NBc];
    bool used[NBc];
    for (int i = 0; i < NBc; i++) { sc[i] = rA_scores[b * NBc + i]; used[i] = false; }
    int chosen[TOPKc];
    for (int t = 0; t < TOPKc; t++) {
        int best = -1; float bv = -INFINITY;
        for (int i = 0; i < NBc; i++)
            if (!used[i] && sc[i] > bv) { bv = sc[i]; best = i; }
        used[best] = true;
        chosen[t] = best;
    }
    for (int i = 0; i < TOPKc; i++)
        for (int jj = i + 1; jj < TOPKc; jj++)
            if (chosen[jj] < chosen[i]) { int tmp = chosen[i]; chosen[i] = chosen[jj]; chosen[jj] = tmp; }
    for (int i = 0; i < TOPKc; i++) rA_sel[b * TOPKc + i] = chosen[i];
}

// ---------------- v mean over S (fallback for fully-masked rows) -----------
__global__ void __launch_bounds__(256) rA_vmeank() {
    int idx = blockIdx.x * blockDim.x + threadIdx.x;
    if (idx >= Bc * Dc) return;
    int b = idx >> 10, d = idx & (Dc - 1);
    const float* base = rA_kv + (size_t)b * Sc * (2 * Dc) + Dc + d;
    float sum = 0.f;
#pragma unroll 8
    for (int s = 0; s < Sc; s++) sum += base[(size_t)s * (2 * Dc)];
    rA_vmean[idx] = sum * (1.0f / (float)Sc);
}

// ---------------- attention: NEG-SIN half-split rope (measured winner) -----
// q' = [q1 c + q2 s, q2 c - q1 s]; k' likewise at key position.
__global__ void __launch_bounds__(64) rA_attn_kernel() {
    __shared__ float qr[64];
    __shared__ float sc[TOPKc * 64];
    __shared__ float red[64];
    __shared__ int   sel_s[TOPKc];

    int lin  = blockIdx.x;              // 0 .. B*H*S-1
    int qpos = lin & (Sc - 1);
    int h    = (lin >> 11) & (Hc - 1);
    int b    = lin >> 15;
    int t    = threadIdx.x;             // 0..63

    if (t < TOPKc) sel_s[t] = rA_sel[b * TOPKc + t];

    const float* qrow = rA_q + (size_t)(b * Sc + qpos) * Dc + h * HDc;
    if (t < 32) {
        float c  = rA_cos[qpos * 32 + t];
        float sn = rA_sin[qpos * 32 + t];
        float q1 = qrow[t], q2 = qrow[t + 32];
        qr[t]      = q1 * c + q2 * sn;      // neg-sin convention
        qr[t + 32] = q2 * c - q1 * sn;
    }
    __syncthreads();

#pragma unroll
    for (int ib = 0; ib < TOPKc; ib++) {
        int key = sel_s[ib] * 64 + t;
        float s = -INFINITY;
        if (key <= qpos) {
            const float* krow = rA_kv + (size_t)(b * Sc + key) * (2 * Dc) + h * HDc;
            const float* ct = rA_cos + key * 32;
            const float* st = rA_sin + key * 32;
            float acc = 0.f;
#pragma unroll
            for (int j = 0; j < 32; j++) {
                float c = ct[j], sn = st[j];
                float k1 = krow[j], k2 = krow[j + 32];
                acc += qr[j] * (k1 * c + k2 * sn) + qr[j + 32] * (k2 * c - k1 * sn);
            }
            s = acc * 0.125f;
        }
        sc[ib * 64 + t] = s;
    }
    __syncthreads();

    float mx = fmaxf(fmaxf(sc[t], sc[64 + t]), fmaxf(sc[128 + t], sc[192 + t]));
    red[t] = mx;
    __syncthreads();
    for (int off = 32; off; off >>= 1) {
        if (t < off) red[t] = fmaxf(red[t], red[t + off]);
        __syncthreads();
    }
    float m = red[0];
    __syncthreads();

    float* outp = rA_ao + (size_t)(b * Sc + qpos) * Dc + h * HDc + t;
    if (m == -INFINITY) {
        *outp = rA_vmean[b * Dc + h * HDc + t];
        return;
    }

    float lsum = 0.f;
#pragma unroll
    for (int ib = 0; ib < TOPKc; ib++) {
        float p = expf(sc[ib * 64 + t] - m);
        sc[ib * 64 + t] = p;
        lsum += p;
    }
    red[t] = lsum;
    __syncthreads();
    for (int off = 32; off; off >>= 1) {
        if (t < off) red[t] += red[t + off];
        __syncthreads();
    }
    float l = red[0];

    float o = 0.f;
    for (int ib = 0; ib < TOPKc; ib++) {
        int kb = sel_s[ib];
        if (kb * 64 > qpos) break;
        const float* vg = rA_kv + (size_t)(b * Sc + kb * 64) * (2 * Dc) + Dc + h * HDc + t;
        int kmax = min(63, qpos - kb * 64);
        for (int c = 0; c <= kmax; c++)
            o += sc[ib * 64 + c] * vg[(size_t)c * (2 * Dc)];
    }
    *outp = o / l;
}

// ---------------- launch ----------------
extern "C" void kernel_launch(void* const* d_in, const int* in_sizes, int n_in,
                              void* d_out, int out_size) {
    const float* x         = (const float*)d_in[0];
    const float* w_q       = (const float*)d_in[1];
    const float* w_kv_down = (const float*)d_in[2];
    const float* w_kv_up   = (const float*)d_in[3];
    const float* w_out     = (const float*)d_in[4];
    const float* w_scorer  = (const float*)d_in[5];
    float* out = (float*)d_out;

    float *q, *lat, *kv, *attn;
    cudaGetSymbolAddress((void**)&q,    rA_q);
    cudaGetSymbolAddress((void**)&lat,  rA_lat);
    cudaGetSymbolAddress((void**)&kv,   rA_kv);
    cudaGetSymbolAddress((void**)&attn, rA_ao);

    const int M = Bc * Sc;  // 4096

    rA_gemm<<<dim3(Dc / 64, M / 64), 256>>>(x, w_q, q, M, Dc, Dc);
    rA_gemm<<<dim3(Rc / 64, M / 64), 256>>>(x, w_kv_down, lat, M, Rc, Dc);
    rA_gemm<<<dim3((2 * Dc) / 64, M / 64), 256>>>(lat, w_kv_up, kv, M, 2 * Dc, Rc);
    rA_tables<<<(Sc * 32 + 255) / 256, 256>>>();
    rA_scorer<<<Bc * NBc, 256>>>(x, w_scorer);
    rA_topk<<<1, 32>>>();
    rA_vmeank<<<(Bc * Dc + 255) / 256, 256>>>();
    rA_attn_kernel<<<Bc * Hc * Sc, 64>>>();
    rA_gemm<<<dim3(Dc / 64, M / 64), 256>>>(attn, w_out, out, M, Dc, Dc);
}

// round 12
// speedup vs baseline: 4.5834x; 4.5834x over previous
#include <cuda_runtime.h>
#include <math.h>

#define Bc 2
#define Sc 2048
#define Dc 1024
#define Hc 16
#define HDc 64
#define Rc 128
#define NBc 32
#define TOPKc 4

// ---------------- scratch (no device allocs) ----------------
__device__ float rB_q[Bc*Sc*Dc];
__device__ float rB_lat[Bc*Sc*Rc];
__device__ float rB_kv[Bc*Sc*2*Dc];
__device__ float rB_ao[Bc*Sc*Dc];
__device__ float rB_scores[Bc*NBc];
__device__ int   rB_sel[Bc*TOPKc];
__device__ float rB_vmean[Bc*Dc];
__device__ float rB_cos[Sc*32];
__device__ float rB_sin[Sc*32];

// ---------------- SGEMM NT 128x128/BK8, 8x8 microtile ----------------------
// C[M,N] = A[M,K] * B[N,K]^T. 256 threads. All dims multiples of 128 (K>=8).
__global__ void __launch_bounds__(256) rB_gemm(const float* __restrict__ A,
                                               const float* __restrict__ Bm,
                                               float* __restrict__ C,
                                               int M, int N, int K) {
    __shared__ float As[8][132];
    __shared__ float Bs[8][132];
    const int t  = threadIdx.x;
    const int m0 = blockIdx.y * 128;
    const int n0 = blockIdx.x * 128;
    const int tx = t & 15, ty = t >> 4;
    const int lrow = t >> 1;          // 0..127
    const int lcol = (t & 1) << 2;    // 0 or 4
    const float* Ag = A + (size_t)(m0 + lrow) * K + lcol;
    const float* Bg = Bm + (size_t)(n0 + lrow) * K + lcol;

    float acc[8][8];
#pragma unroll
    for (int i = 0; i < 8; i++)
#pragma unroll
        for (int j = 0; j < 8; j++) acc[i][j] = 0.f;

    for (int k0 = 0; k0 < K; k0 += 8) {
        float4 av = *(const float4*)(Ag + k0);
        float4 bv = *(const float4*)(Bg + k0);
        As[lcol+0][lrow] = av.x; As[lcol+1][lrow] = av.y;
        As[lcol+2][lrow] = av.z; As[lcol+3][lrow] = av.w;
        Bs[lcol+0][lrow] = bv.x; Bs[lcol+1][lrow] = bv.y;
        Bs[lcol+2][lrow] = bv.z; Bs[lcol+3][lrow] = bv.w;
        __syncthreads();
#pragma unroll
        for (int kk = 0; kk < 8; kk++) {
            float a[8], b[8];
            float4 a0 = *(const float4*)&As[kk][ty << 3];
            float4 a1 = *(const float4*)&As[kk][(ty << 3) + 4];
            float4 b0 = *(const float4*)&Bs[kk][tx << 3];
            float4 b1 = *(const float4*)&Bs[kk][(tx << 3) + 4];
            a[0]=a0.x; a[1]=a0.y; a[2]=a0.z; a[3]=a0.w;
            a[4]=a1.x; a[5]=a1.y; a[6]=a1.z; a[7]=a1.w;
            b[0]=b0.x; b[1]=b0.y; b[2]=b0.z; b[3]=b0.w;
            b[4]=b1.x; b[5]=b1.y; b[6]=b1.z; b[7]=b1.w;
#pragma unroll
            for (int i = 0; i < 8; i++)
#pragma unroll
                for (int j = 0; j < 8; j++) acc[i][j] += a[i] * b[j];
        }
        __syncthreads();
    }
#pragma unroll
    for (int i = 0; i < 8; i++) {
        float* crow = C + (size_t)(m0 + (ty << 3) + i) * N + n0 + (tx << 3);
        *(float4*)crow       = make_float4(acc[i][0], acc[i][1], acc[i][2], acc[i][3]);
        *(float4*)(crow + 4) = make_float4(acc[i][4], acc[i][5], acc[i][6], acc[i][7]);
    }
}

// ---------------- rope tables ----------------------------------------------
__global__ void __launch_bounds__(256) rB_tables() {
    int idx = blockIdx.x * blockDim.x + threadIdx.x;
    if (idx >= Sc * 32) return;
    int s = idx >> 5;
    int j = idx & 31;
    double invf = pow(100000.0, -((double)(2 * j)) / 64.0);
    float ang = (float)s * (float)invf;
    double cd, sd;
    sincos((double)ang, &cd, &sd);
    rB_cos[idx] = (float)cd;
    rB_sin[idx] = (float)sd;
}

// ---------------- rope apply ONCE (neg-sin), in place on q and k -----------
// grid B*S, 512 threads: thread = (h, j)
__global__ void __launch_bounds__(512) rB_rope() {
    int row = blockIdx.x;
    int s   = row & (Sc - 1);
    int t   = threadIdx.x;
    int h   = t >> 5;
    int j   = t & 31;
    float c  = rB_cos[s * 32 + j];
    float sn = rB_sin[s * 32 + j];

    float* qp = rB_q + (size_t)row * Dc + h * HDc + j;
    float a = qp[0], b2 = qp[32];
    qp[0]  = a * c + b2 * sn;     // neg-sin convention (measured)
    qp[32] = b2 * c - a * sn;

    float* kp = rB_kv + (size_t)row * (2 * Dc) + h * HDc + j;
    a = kp[0]; b2 = kp[32];
    kp[0]  = a * c + b2 * sn;
    kp[32] = b2 * c - a * sn;
}

// ---------------- block scorer ----------------
__global__ void __launch_bounds__(256) rB_scorer(const float* __restrict__ x,
                                                 const float* __restrict__ w_scorer) {
    int bj = blockIdx.x;
    int b = bj >> 5, j = bj & 31;
    const float* base = x + (size_t)(b * Sc + j * 64) * Dc;
    float sum = 0.f;
    for (int i = threadIdx.x; i < 64 * Dc; i += 256)
        sum += base[i] * w_scorer[i & (Dc - 1)];
    __shared__ float red[256];
    red[threadIdx.x] = sum;
    __syncthreads();
    for (int off = 128; off; off >>= 1) {
        if (threadIdx.x < off) red[threadIdx.x] += red[threadIdx.x + off];
        __syncthreads();
    }
    if (threadIdx.x == 0) rB_scores[bj] = red[0] * (1.0f / 64.0f);
}

// ---------------- top-k ----------------
__global__ void rB_topk() {
    int b = threadIdx.x;
    if (b >= Bc) return;
    float sc[NBc];
    bool used[NBc];
    for (int i = 0; i < NBc; i++) { sc[i] = rB_scores[b * NBc + i]; used[i] = false; }
    int chosen[TOPKc];
    for (int t = 0; t < TOPKc; t++) {
        int best = -1; float bv = -INFINITY;
        for (int i = 0; i < NBc; i++)
            if (!used[i] && sc[i] > bv) { bv = sc[i]; best = i; }
        used[best] = true;
        chosen[t] = best;
    }
    for (int i = 0; i < TOPKc; i++)
        for (int jj = i + 1; jj < TOPKc; jj++)
            if (chosen[jj] < chosen[i]) { int tmp = chosen[i]; chosen[i] = chosen[jj]; chosen[jj] = tmp; }
    for (int i = 0; i < TOPKc; i++) rB_sel[b * TOPKc + i] = chosen[i];
}

// ---------------- v mean over S ----------------
__global__ void __launch_bounds__(256) rB_vmeank() {
    int idx = blockIdx.x * blockDim.x + threadIdx.x;
    if (idx >= Bc * Dc) return;
    int b = idx >> 10, d = idx & (Dc - 1);
    const float* base = rB_kv + (size_t)b * Sc * (2 * Dc) + Dc + d;
    float sum = 0.f;
#pragma unroll 8
    for (int s = 0; s < Sc; s++) sum += base[(size_t)s * (2 * Dc)];
    rB_vmean[idx] = sum * (1.0f / (float)Sc);
}

// ---------------- tiled flash attention (round-1 machinery, certified) -----
// One CTA per (b, h, q-tile of 64). 256 threads: (ty,tx) own 4x4 patch.
__global__ void __launch_bounds__(256) rB_attn() {
    extern __shared__ float sm[];
    float* Qs = sm;               // 64*68
    float* KV = sm + 64 * 68;     // 64*68
    float* Ps = sm + 2 * 64 * 68; // 64*68

    int lin = blockIdx.x;
    int qt = lin & 31;
    int h  = (lin >> 5) & (Hc - 1);
    int b  = lin >> 9;
    int t  = threadIdx.x;
    int ty = t >> 4, tx = t & 15;
    int r0 = ty << 2, c0 = tx << 2;

    __shared__ int sel_s[TOPKc];
    if (t < TOPKc) sel_s[t] = rB_sel[b * TOPKc + t];
    __syncthreads();
    int min_sel = sel_s[0];

    if (qt < min_sel) {
        float4 vm = *(const float4*)&rB_vmean[b * Dc + h * HDc + c0];
#pragma unroll
        for (int i = 0; i < 4; i++)
            *(float4*)&rB_ao[(size_t)(b * Sc + qt * 64 + r0 + i) * Dc + h * HDc + c0] = vm;
        return;
    }

    const float* qg = rB_q + (size_t)(b * Sc + qt * 64) * Dc + h * HDc;
#pragma unroll
    for (int rr = 0; rr < 4; rr++) {
        int slot = t + 256 * rr;
        int row  = slot >> 4;
        int cc   = (slot & 15) << 2;
        *(float4*)&Qs[row * 68 + cc] = *(const float4*)(qg + (size_t)row * Dc + cc);
    }

    float m[4], l[4], o[4][4];
#pragma unroll
    for (int i = 0; i < 4; i++) {
        m[i] = -INFINITY; l[i] = 0.f;
#pragma unroll
        for (int j = 0; j < 4; j++) o[i][j] = 0.f;
    }

    for (int ib = 0; ib < TOPKc; ib++) {
        int kb = sel_s[ib];
        if (kb > qt) break;
        const float* kg = rB_kv + (size_t)(b * Sc + kb * 64) * (2 * Dc) + h * HDc;

        __syncthreads();
#pragma unroll
        for (int rr = 0; rr < 4; rr++) {
            int slot = t + 256 * rr;
            int row  = slot >> 4;
            int cc   = (slot & 15) << 2;
            float4 v = *(const float4*)(kg + (size_t)row * (2 * Dc) + cc);
            KV[(cc + 0) * 68 + row] = v.x;
            KV[(cc + 1) * 68 + row] = v.y;
            KV[(cc + 2) * 68 + row] = v.z;
            KV[(cc + 3) * 68 + row] = v.w;
        }
        __syncthreads();

        float s[4][4];
#pragma unroll
        for (int i = 0; i < 4; i++)
#pragma unroll
            for (int j = 0; j < 4; j++) s[i][j] = 0.f;
#pragma unroll 16
        for (int d = 0; d < 64; d++) {
            float4 k4 = *(const float4*)&KV[d * 68 + c0];
            float q0 = Qs[(r0 + 0) * 68 + d];
            float q1 = Qs[(r0 + 1) * 68 + d];
            float q2 = Qs[(r0 + 2) * 68 + d];
            float q3 = Qs[(r0 + 3) * 68 + d];
            s[0][0] += q0 * k4.x; s[0][1] += q0 * k4.y; s[0][2] += q0 * k4.z; s[0][3] += q0 * k4.w;
            s[1][0] += q1 * k4.x; s[1][1] += q1 * k4.y; s[1][2] += q1 * k4.z; s[1][3] += q1 * k4.w;
            s[2][0] += q2 * k4.x; s[2][1] += q2 * k4.y; s[2][2] += q2 * k4.z; s[2][3] += q2 * k4.w;
            s[3][0] += q3 * k4.x; s[3][1] += q3 * k4.y; s[3][2] += q3 * k4.z; s[3][3] += q3 * k4.w;
        }
        bool diag = (kb == qt);
#pragma unroll
        for (int i = 0; i < 4; i++)
#pragma unroll
            for (int j = 0; j < 4; j++) {
                s[i][j] *= 0.125f;
                if (diag && (c0 + j) > (r0 + i)) s[i][j] = -INFINITY;
            }

#pragma unroll
        for (int i = 0; i < 4; i++) {
            float v = fmaxf(fmaxf(s[i][0], s[i][1]), fmaxf(s[i][2], s[i][3]));
#pragma unroll
            for (int off = 8; off; off >>= 1)
                v = fmaxf(v, __shfl_xor_sync(0xffffffffu, v, off, 16));
            float mnew = fmaxf(m[i], v);
            float alpha = expf(m[i] - mnew);
            float p0 = expf(s[i][0] - mnew);
            float p1 = expf(s[i][1] - mnew);
            float p2 = expf(s[i][2] - mnew);
            float p3 = expf(s[i][3] - mnew);
            float rv = p0 + p1 + p2 + p3;
#pragma unroll
            for (int off = 8; off; off >>= 1)
                rv += __shfl_xor_sync(0xffffffffu, rv, off, 16);
            l[i] = l[i] * alpha + rv;
            m[i] = mnew;
            o[i][0] *= alpha; o[i][1] *= alpha; o[i][2] *= alpha; o[i][3] *= alpha;
            *(float4*)&Ps[(r0 + i) * 68 + c0] = make_float4(p0, p1, p2, p3);
        }
        __syncthreads();

#pragma unroll
        for (int rr = 0; rr < 4; rr++) {
            int slot = t + 256 * rr;
            int row  = slot >> 4;
            int cc   = (slot & 15) << 2;
            *(float4*)&KV[row * 68 + cc] =
                *(const float4*)(kg + Dc + (size_t)row * (2 * Dc) + cc);
        }
        __syncthreads();

#pragma unroll 16
        for (int k = 0; k < 64; k++) {
            float4 v4 = *(const float4*)&KV[k * 68 + c0];
            float p0 = Ps[(r0 + 0) * 68 + k];
            float p1 = Ps[(r0 + 1) * 68 + k];
            float p2 = Ps[(r0 + 2) * 68 + k];
            float p3 = Ps[(r0 + 3) * 68 + k];
            o[0][0] += p0 * v4.x; o[0][1] += p0 * v4.y; o[0][2] += p0 * v4.z; o[0][3] += p0 * v4.w;
            o[1][0] += p1 * v4.x; o[1][1] += p1 * v4.y; o[1][2] += p1 * v4.z; o[1][3] += p1 * v4.w;
            o[2][0] += p2 * v4.x; o[2][1] += p2 * v4.y; o[2][2] += p2 * v4.z; o[2][3] += p2 * v4.w;
            o[3][0] += p3 * v4.x; o[3][1] += p3 * v4.y; o[3][2] += p3 * v4.z; o[3][3] += p3 * v4.w;
        }
    }

#pragma unroll
    for (int i = 0; i < 4; i++) {
        float inv = 1.0f / l[i];
        float4 v = make_float4(o[i][0] * inv, o[i][1] * inv, o[i][2] * inv, o[i][3] * inv);
        *(float4*)&rB_ao[(size_t)(b * Sc + qt * 64 + r0 + i) * Dc + h * HDc + c0] = v;
    }
}

// ---------------- launch ----------------
extern "C" void kernel_launch(void* const* d_in, const int* in_sizes, int n_in,
                              void* d_out, int out_size) {
    const float* x         = (const float*)d_in[0];
    const float* w_q       = (const float*)d_in[1];
    const float* w_kv_down = (const float*)d_in[2];
    const float* w_kv_up   = (const float*)d_in[3];
    const float* w_out     = (const float*)d_in[4];
    const float* w_scorer  = (const float*)d_in[5];
    float* out = (float*)d_out;

    float *q, *lat, *kv, *attn;
    cudaGetSymbolAddress((void**)&q,    rB_q);
    cudaGetSymbolAddress((void**)&lat,  rB_lat);
    cudaGetSymbolAddress((void**)&kv,   rB_kv);
    cudaGetSymbolAddress((void**)&attn, rB_ao);

    const int M = Bc * Sc;  // 4096

    rB_gemm<<<dim3(Dc / 128, M / 128), 256>>>(x, w_q, q, M, Dc, Dc);
    rB_gemm<<<dim3(Rc / 128, M / 128), 256>>>(x, w_kv_down, lat, M, Rc, Dc);
    rB_gemm<<<dim3((2 * Dc) / 128, M / 128), 256>>>(lat, w_kv_up, kv, M, 2 * Dc, Rc);
    rB_tables<<<(Sc * 32 + 255) / 256, 256>>>();
    rB_rope<<<M, 512>>>();
    rB_scorer<<<Bc * NBc, 256>>>(x, w_scorer);
    rB_topk<<<1, 32>>>();
    rB_vmeank<<<(Bc * Dc + 255) / 256, 256>>>();
    int smem = 3 * 64 * 68 * sizeof(float);  // 52224 B
    cudaFuncSetAttribute(rB_attn, cudaFuncAttributeMaxDynamicSharedMemorySize, smem);
    rB_attn<<<Bc * Hc * (Sc / 64), 256, smem>>>();
    rB_gemm<<<dim3(Dc / 128, M / 128), 256>>>(attn, w_out, out, M, Dc, Dc);
}

// round 14
// speedup vs baseline: 7.1227x; 1.5540x over previous
#include <cuda_runtime.h>
#include <cuda_bf16.h>
#include <math.h>
#include <stdint.h>

#define Bc 2
#define Sc 2048
#define Dc 1024
#define Hc 16
#define HDc 64
#define Rc 128
#define NBc 32
#define TOPKc 4

// ---------------- scratch (no device allocs) ----------------
__device__ float rD_q[Bc*Sc*Dc];
__device__ float rD_lat[Bc*Sc*Rc];
__device__ float rD_kv[Bc*Sc*2*Dc];
__device__ float rD_ao[Bc*Sc*Dc];
__device__ float rD_scores[Bc*NBc];
__device__ int   rD_sel[Bc*TOPKc];
__device__ float rD_vmean[Bc*Dc];
__device__ float rD_cos[Sc*32];
__device__ float rD_sin[Sc*32];
// bf16 hi/lo splits
__device__ __nv_bfloat16 rD_xh[Bc*Sc*Dc],   rD_xl[Bc*Sc*Dc];
__device__ __nv_bfloat16 rD_wqh[Dc*Dc],     rD_wql[Dc*Dc];
__device__ __nv_bfloat16 rD_wkdh[Rc*Dc],    rD_wkdl[Rc*Dc];
__device__ __nv_bfloat16 rD_wkuh[2*Dc*Rc],  rD_wkul[2*Dc*Rc];
__device__ __nv_bfloat16 rD_woh[Dc*Dc],     rD_wol[Dc*Dc];
__device__ __nv_bfloat16 rD_lath[Bc*Sc*Rc], rD_latl[Bc*Sc*Rc];
__device__ __nv_bfloat16 rD_aoh[Bc*Sc*Dc],  rD_aol[Bc*Sc*Dc];

// ---------------- fp32 -> bf16 hi/lo split ----------------
__global__ void __launch_bounds__(256) rD_split(const float* __restrict__ src,
                                                __nv_bfloat16* __restrict__ h,
                                                __nv_bfloat16* __restrict__ l,
                                                int n) {
    int i = blockIdx.x * blockDim.x + threadIdx.x;
    if (i >= n) return;
    float a = src[i];
    __nv_bfloat16 hh = __float2bfloat16(a);
    h[i] = hh;
    l[i] = __float2bfloat16(a - __bfloat162float(hh));
}

// ---------------- mma.sync helper ----------------
__device__ __forceinline__ void rD_mma(float* d, const uint32_t* a, const uint32_t* b) {
    asm volatile(
        "mma.sync.aligned.m16n8k16.row.col.f32.bf16.bf16.f32 "
        "{%0,%1,%2,%3}, {%4,%5,%6,%7}, {%8,%9}, {%0,%1,%2,%3};\n"
        : "+f"(d[0]), "+f"(d[1]), "+f"(d[2]), "+f"(d[3])
        : "r"(a[0]), "r"(a[1]), "r"(a[2]), "r"(a[3]), "r"(b[0]), "r"(b[1]));
}

// ---------------- HMMA split-bf16 GEMM NT ----------------
// C[M,N] = (Ah+Al)[M,K] * (Bh+Bl)[N,K]^T (Al*Bl dropped).
// M,N multiples of 128; K multiple of 32. 256 threads = 8 warps (2Mx4N),
// warp tile 64x32, m16n8k16 fragments loaded straight from padded smem.
#define RD_STRIDE 40   // bf16 elements per smem row (32 + 8 pad) -> conflict-free
__global__ void __launch_bounds__(256) rD_mmagemm(
    const __nv_bfloat16* __restrict__ Ah, const __nv_bfloat16* __restrict__ Al,
    const __nv_bfloat16* __restrict__ Bh, const __nv_bfloat16* __restrict__ Bl,
    float* __restrict__ C, int M, int N, int K) {
    __shared__ __nv_bfloat16 sAh[128 * RD_STRIDE], sAl[128 * RD_STRIDE];
    __shared__ __nv_bfloat16 sBh[128 * RD_STRIDE], sBl[128 * RD_STRIDE];

    const int t    = threadIdx.x;
    const int lane = t & 31;
    const int w    = t >> 5;
    const int wm   = w >> 2;      // 0..1
    const int wn   = w & 3;       // 0..3
    const int m0   = blockIdx.y * 128;
    const int n0   = blockIdx.x * 128;
    const int lr   = lane >> 2;          // 0..7
    const int lc   = (lane & 3) * 2;     // 0,2,4,6

    float acc[4][4][4];
#pragma unroll
    for (int i = 0; i < 4; i++)
#pragma unroll
        for (int j = 0; j < 4; j++)
#pragma unroll
            for (int k = 0; k < 4; k++) acc[i][j][k] = 0.f;

    for (int k0 = 0; k0 < K; k0 += 32) {
        // stage 4 tiles (128 rows x 32 bf16 each)
#pragma unroll
        for (int i = 0; i < 2; i++) {
            int idx = t + i * 256;        // 0..511
            int r   = idx >> 2;           // 0..127
            int c8  = (idx & 3) * 8;      // 0,8,16,24
            size_t ga = (size_t)(m0 + r) * K + k0 + c8;
            size_t gb = (size_t)(n0 + r) * K + k0 + c8;
            *(uint4*)&sAh[r * RD_STRIDE + c8] = *(const uint4*)&Ah[ga];
            *(uint4*)&sAl[r * RD_STRIDE + c8] = *(const uint4*)&Al[ga];
            *(uint4*)&sBh[r * RD_STRIDE + c8] = *(const uint4*)&Bh[gb];
            *(uint4*)&sBl[r * RD_STRIDE + c8] = *(const uint4*)&Bl[gb];
        }
        __syncthreads();

#pragma unroll
        for (int ks = 0; ks < 2; ks++) {
            const int kk = ks * 16 + lc;
            uint32_t ah[4][4], al[4][4], bh[4][2], bl[4][2];
#pragma unroll
            for (int mt = 0; mt < 4; mt++) {
                int r = wm * 64 + mt * 16 + lr;
                ah[mt][0] = *(const uint32_t*)&sAh[r * RD_STRIDE + kk];
                ah[mt][1] = *(const uint32_t*)&sAh[(r + 8) * RD_STRIDE + kk];
                ah[mt][2] = *(const uint32_t*)&sAh[r * RD_STRIDE + kk + 8];
                ah[mt][3] = *(const uint32_t*)&sAh[(r + 8) * RD_STRIDE + kk + 8];
                al[mt][0] = *(const uint32_t*)&sAl[r * RD_STRIDE + kk];
                al[mt][1] = *(const uint32_t*)&sAl[(r + 8) * RD_STRIDE + kk];
                al[mt][2] = *(const uint32_t*)&sAl[r * RD_STRIDE + kk + 8];
                al[mt][3] = *(const uint32_t*)&sAl[(r + 8) * RD_STRIDE + kk + 8];
            }
#pragma unroll
            for (int nt = 0; nt < 4; nt++) {
                int r = wn * 32 + nt * 8 + lr;
                bh[nt][0] = *(const uint32_t*)&sBh[r * RD_STRIDE + kk];
                bh[nt][1] = *(const uint32_t*)&sBh[r * RD_STRIDE + kk + 8];
                bl[nt][0] = *(const uint32_t*)&sBl[r * RD_STRIDE + kk];
                bl[nt][1] = *(const uint32_t*)&sBl[r * RD_STRIDE + kk + 8];
            }
#pragma unroll
            for (int mt = 0; mt < 4; mt++)
#pragma unroll
                for (int nt = 0; nt < 4; nt++) {
                    rD_mma(acc[mt][nt], ah[mt], bh[nt]);
                    rD_mma(acc[mt][nt], ah[mt], bl[nt]);
                    rD_mma(acc[mt][nt], al[mt], bh[nt]);
                }
        }
        __syncthreads();
    }

    // epilogue
#pragma unroll
    for (int mt = 0; mt < 4; mt++) {
#pragma unroll
        for (int nt = 0; nt < 4; nt++) {
            int row = m0 + wm * 64 + mt * 16 + lr;
            int col = n0 + wn * 32 + nt * 8 + lc;
            float* c0 = C + (size_t)row * N + col;
            c0[0] = acc[mt][nt][0];
            c0[1] = acc[mt][nt][1];
            float* c2 = C + (size_t)(row + 8) * N + col;
            c2[0] = acc[mt][nt][2];
            c2[1] = acc[mt][nt][3];
        }
    }
}

// ---------------- rope tables ----------------
__global__ void __launch_bounds__(256) rD_tables() {
    int idx = blockIdx.x * blockDim.x + threadIdx.x;
    if (idx >= Sc * 32) return;
    int s = idx >> 5;
    int j = idx & 31;
    double invf = pow(100000.0, -((double)(2 * j)) / 64.0);
    float ang = (float)s * (float)invf;
    double cd, sd;
    sincos((double)ang, &cd, &sd);
    rD_cos[idx] = (float)cd;
    rD_sin[idx] = (float)sd;
}

// ---------------- rope apply once (neg-sin convention, measured) ----------
__global__ void __launch_bounds__(512) rD_rope() {
    int row = blockIdx.x;
    int s   = row & (Sc - 1);
    int t   = threadIdx.x;
    int h   = t >> 5;
    int j   = t & 31;
    float c  = rD_cos[s * 32 + j];
    float sn = rD_sin[s * 32 + j];

    float* qp = rD_q + (size_t)row * Dc + h * HDc + j;
    float a = qp[0], b2 = qp[32];
    qp[0]  = a * c + b2 * sn;
    qp[32] = b2 * c - a * sn;

    float* kp = rD_kv + (size_t)row * (2 * Dc) + h * HDc + j;
    a = kp[0]; b2 = kp[32];
    kp[0]  = a * c + b2 * sn;
    kp[32] = b2 * c - a * sn;
}

// ---------------- block scorer ----------------
__global__ void __launch_bounds__(256) rD_scorer(const float* __restrict__ x,
                                                 const float* __restrict__ w_scorer) {
    int bj = blockIdx.x;
    int b = bj >> 5, j = bj & 31;
    const float* base = x + (size_t)(b * Sc + j * 64) * Dc;
    float sum = 0.f;
    for (int i = threadIdx.x; i < 64 * Dc; i += 256)
        sum += base[i] * w_scorer[i & (Dc - 1)];
    __shared__ float red[256];
    red[threadIdx.x] = sum;
    __syncthreads();
    for (int off = 128; off; off >>= 1) {
        if (threadIdx.x < off) red[threadIdx.x] += red[threadIdx.x + off];
        __syncthreads();
    }
    if (threadIdx.x == 0) rD_scores[bj] = red[0] * (1.0f / 64.0f);
}

// ---------------- top-k ----------------
__global__ void rD_topk() {
    int b = threadIdx.x;
    if (b >= Bc) return;
    float sc[NBc];
    bool used[NBc];
    for (int i = 0; i < NBc; i++) { sc[i] = rD_scores[b * NBc + i]; used[i] = false; }
    int chosen[TOPKc];
    for (int t = 0; t < TOPKc; t++) {
        int best = -1; float bv = -INFINITY;
        for (int i = 0; i < NBc; i++)
            if (!used[i] && sc[i] > bv) { bv = sc[i]; best = i; }
        used[best] = true;
        chosen[t] = best;
    }
    for (int i = 0; i < TOPKc; i++)
        for (int jj = i + 1; jj < TOPKc; jj++)
            if (chosen[jj] < chosen[i]) { int tmp = chosen[i]; chosen[i] = chosen[jj]; chosen[jj] = tmp; }
    for (int i = 0; i < TOPKc; i++) rD_sel[b * TOPKc + i] = chosen[i];
}

// ---------------- v mean over S ----------------
__global__ void __launch_bounds__(256) rD_vmeank() {
    int idx = blockIdx.x * blockDim.x + threadIdx.x;
    if (idx >= Bc * Dc) return;
    int b = idx >> 10, d = idx & (Dc - 1);
    const float* base = rD_kv + (size_t)b * Sc * (2 * Dc) + Dc + d;
    float sum = 0.f;
#pragma unroll 8
    for (int s = 0; s < Sc; s++) sum += base[(size_t)s * (2 * Dc)];
    rD_vmean[idx] = sum * (1.0f / (float)Sc);
}

// ---------------- tiled flash attention (certified machinery) ----------
__global__ void __launch_bounds__(256) rD_attn() {
    extern __shared__ float sm[];
    float* Qs = sm;
    float* KV = sm + 64 * 68;
    float* Ps = sm + 2 * 64 * 68;

    int lin = blockIdx.x;
    int qt = lin & 31;
    int h  = (lin >> 5) & (Hc - 1);
    int b  = lin >> 9;
    int t  = threadIdx.x;
    int ty = t >> 4, tx = t & 15;
    int r0 = ty << 2, c0 = tx << 2;

    __shared__ int sel_s[TOPKc];
    if (t < TOPKc) sel_s[t] = rD_sel[b * TOPKc + t];
    __syncthreads();
    int min_sel = sel_s[0];

    if (qt < min_sel) {
        float4 vm = *(const float4*)&rD_vmean[b * Dc + h * HDc + c0];
#pragma unroll
        for (int i = 0; i < 4; i++)
            *(float4*)&rD_ao[(size_t)(b * Sc + qt * 64 + r0 + i) * Dc + h * HDc + c0] = vm;
        return;
    }

    const float* qg = rD_q + (size_t)(b * Sc + qt * 64) * Dc + h * HDc;
#pragma unroll
    for (int rr = 0; rr < 4; rr++) {
        int slot = t + 256 * rr;
        int row  = slot >> 4;
        int cc   = (slot & 15) << 2;
        *(float4*)&Qs[row * 68 + cc] = *(const float4*)(qg + (size_t)row * Dc + cc);
    }

    float m[4], l[4], o[4][4];
#pragma unroll
    for (int i = 0; i < 4; i++) {
        m[i] = -INFINITY; l[i] = 0.f;
#pragma unroll
        for (int j = 0; j < 4; j++) o[i][j] = 0.f;
    }

    for (int ib = 0; ib < TOPKc; ib++) {
        int kb = sel_s[ib];
        if (kb > qt) break;
        const float* kg = rD_kv + (size_t)(b * Sc + kb * 64) * (2 * Dc) + h * HDc;

        __syncthreads();
#pragma unroll
        for (int rr = 0; rr < 4; rr++) {
            int slot = t + 256 * rr;
            int row  = slot >> 4;
            int cc   = (slot & 15) << 2;
            float4 v = *(const float4*)(kg + (size_t)row * (2 * Dc) + cc);
            KV[(cc + 0) * 68 + row] = v.x;
            KV[(cc + 1) * 68 + row] = v.y;
            KV[(cc + 2) * 68 + row] = v.z;
            KV[(cc + 3) * 68 + row] = v.w;
        }
        __syncthreads();

        float s[4][4];
#pragma unroll
        for (int i = 0; i < 4; i++)
#pragma unroll
            for (int j = 0; j < 4; j++) s[i][j] = 0.f;
#pragma unroll 16
        for (int d = 0; d < 64; d++) {
            float4 k4 = *(const float4*)&KV[d * 68 + c0];
            float q0 = Qs[(r0 + 0) * 68 + d];
            float q1 = Qs[(r0 + 1) * 68 + d];
            float q2 = Qs[(r0 + 2) * 68 + d];
            float q3 = Qs[(r0 + 3) * 68 + d];
            s[0][0] += q0 * k4.x; s[0][1] += q0 * k4.y; s[0][2] += q0 * k4.z; s[0][3] += q0 * k4.w;
            s[1][0] += q1 * k4.x; s[1][1] += q1 * k4.y; s[1][2] += q1 * k4.z; s[1][3] += q1 * k4.w;
            s[2][0] += q2 * k4.x; s[2][1] += q2 * k4.y; s[2][2] += q2 * k4.z; s[2][3] += q2 * k4.w;
            s[3][0] += q3 * k4.x; s[3][1] += q3 * k4.y; s[3][2] += q3 * k4.z; s[3][3] += q3 * k4.w;
        }
        bool diag = (kb == qt);
#pragma unroll
        for (int i = 0; i < 4; i++)
#pragma unroll
            for (int j = 0; j < 4; j++) {
                s[i][j] *= 0.125f;
                if (diag && (c0 + j) > (r0 + i)) s[i][j] = -INFINITY;
            }

#pragma unroll
        for (int i = 0; i < 4; i++) {
            float v = fmaxf(fmaxf(s[i][0], s[i][1]), fmaxf(s[i][2], s[i][3]));
#pragma unroll
            for (int off = 8; off; off >>= 1)
                v = fmaxf(v, __shfl_xor_sync(0xffffffffu, v, off, 16));
            float mnew = fmaxf(m[i], v);
            float alpha = expf(m[i] - mnew);
            float p0 = expf(s[i][0] - mnew);
            float p1 = expf(s[i][1] - mnew);
            float p2 = expf(s[i][2] - mnew);
            float p3 = expf(s[i][3] - mnew);
            float rv = p0 + p1 + p2 + p3;
#pragma unroll
            for (int off = 8; off; off >>= 1)
                rv += __shfl_xor_sync(0xffffffffu, rv, off, 16);
            l[i] = l[i] * alpha + rv;
            m[i] = mnew;
            o[i][0] *= alpha; o[i][1] *= alpha; o[i][2] *= alpha; o[i][3] *= alpha;
            *(float4*)&Ps[(r0 + i) * 68 + c0] = make_float4(p0, p1, p2, p3);
        }
        __syncthreads();

#pragma unroll
        for (int rr = 0; rr < 4; rr++) {
            int slot = t + 256 * rr;
            int row  = slot >> 4;
            int cc   = (slot & 15) << 2;
            *(float4*)&KV[row * 68 + cc] =
                *(const float4*)(kg + Dc + (size_t)row * (2 * Dc) + cc);
        }
        __syncthreads();

#pragma unroll 16
        for (int k = 0; k < 64; k++) {
            float4 v4 = *(const float4*)&KV[k * 68 + c0];
            float p0 = Ps[(r0 + 0) * 68 + k];
            float p1 = Ps[(r0 + 1) * 68 + k];
            float p2 = Ps[(r0 + 2) * 68 + k];
            float p3 = Ps[(r0 + 3) * 68 + k];
            o[0][0] += p0 * v4.x; o[0][1] += p0 * v4.y; o[0][2] += p0 * v4.z; o[0][3] += p0 * v4.w;
            o[1][0] += p1 * v4.x; o[1][1] += p1 * v4.y; o[1][2] += p1 * v4.z; o[1][3] += p1 * v4.w;
            o[2][0] += p2 * v4.x; o[2][1] += p2 * v4.y; o[2][2] += p2 * v4.z; o[2][3] += p2 * v4.w;
            o[3][0] += p3 * v4.x; o[3][1] += p3 * v4.y; o[3][2] += p3 * v4.z; o[3][3] += p3 * v4.w;
        }
    }

#pragma unroll
    for (int i = 0; i < 4; i++) {
        float inv = 1.0f / l[i];
        float4 v = make_float4(o[i][0] * inv, o[i][1] * inv, o[i][2] * inv, o[i][3] * inv);
        *(float4*)&rD_ao[(size_t)(b * Sc + qt * 64 + r0 + i) * Dc + h * HDc + c0] = v;
    }
}

// ---------------- launch ----------------
extern "C" void kernel_launch(void* const* d_in, const int* in_sizes, int n_in,
                              void* d_out, int out_size) {
    const float* x         = (const float*)d_in[0];
    const float* w_q       = (const float*)d_in[1];
    const float* w_kv_down = (const float*)d_in[2];
    const float* w_kv_up   = (const float*)d_in[3];
    const float* w_out     = (const float*)d_in[4];
    const float* w_scorer  = (const float*)d_in[5];
    float* out = (float*)d_out;

    float *q, *lat, *kv, *attn;
    cudaGetSymbolAddress((void**)&q,    rD_q);
    cudaGetSymbolAddress((void**)&lat,  rD_lat);
    cudaGetSymbolAddress((void**)&kv,   rD_kv);
    cudaGetSymbolAddress((void**)&attn, rD_ao);
    __nv_bfloat16 *xh, *xl, *wqh, *wql, *wkdh, *wkdl, *wkuh, *wkul, *woh, *wol,
                  *lath, *latl, *aoh, *aol;
    cudaGetSymbolAddress((void**)&xh,   rD_xh);   cudaGetSymbolAddress((void**)&xl,   rD_xl);
    cudaGetSymbolAddress((void**)&wqh,  rD_wqh);  cudaGetSymbolAddress((void**)&wql,  rD_wql);
    cudaGetSymbolAddress((void**)&wkdh, rD_wkdh); cudaGetSymbolAddress((void**)&wkdl, rD_wkdl);
    cudaGetSymbolAddress((void**)&wkuh, rD_wkuh); cudaGetSymbolAddress((void**)&wkul, rD_wkul);
    cudaGetSymbolAddress((void**)&woh,  rD_woh);  cudaGetSymbolAddress((void**)&wol,  rD_wol);
    cudaGetSymbolAddress((void**)&lath, rD_lath); cudaGetSymbolAddress((void**)&latl, rD_latl);
    cudaGetSymbolAddress((void**)&aoh,  rD_aoh);  cudaGetSymbolAddress((void**)&aol,  rD_aol);

    const int M = Bc * Sc;  // 4096
    auto nb = [](int n) { return (n + 255) / 256; };

    // splits of inputs
    rD_split<<<nb(M * Dc), 256>>>(x, xh, xl, M * Dc);
    rD_split<<<nb(Dc * Dc), 256>>>(w_q, wqh, wql, Dc * Dc);
    rD_split<<<nb(Rc * Dc), 256>>>(w_kv_down, wkdh, wkdl, Rc * Dc);
    rD_split<<<nb(2 * Dc * Rc), 256>>>(w_kv_up, wkuh, wkul, 2 * Dc * Rc);
    rD_split<<<nb(Dc * Dc), 256>>>(w_out, woh, wol, Dc * Dc);

    // q = x @ w_q^T ; lat = x @ w_kv_down^T
    rD_mmagemm<<<dim3(Dc / 128, M / 128), 256>>>(xh, xl, wqh, wql, q, M, Dc, Dc);
    rD_mmagemm<<<dim3(Rc / 128, M / 128), 256>>>(xh, xl, wkdh, wkdl, lat, M, Rc, Dc);
    rD_split<<<nb(M * Rc), 256>>>(lat, lath, latl, M * Rc);
    // kv = lat @ w_kv_up^T
    rD_mmagemm<<<dim3((2 * Dc) / 128, M / 128), 256>>>(lath, latl, wkuh, wkul, kv, M, 2 * Dc, Rc);

    rD_tables<<<(Sc * 32 + 255) / 256, 256>>>();
    rD_rope<<<M, 512>>>();
    rD_scorer<<<Bc * NBc, 256>>>(x, w_scorer);
    rD_topk<<<1, 32>>>();
    rD_vmeank<<<(Bc * Dc + 255) / 256, 256>>>();

    int smem = 3 * 64 * 68 * sizeof(float);
    cudaFuncSetAttribute(rD_attn, cudaFuncAttributeMaxDynamicSharedMemorySize, smem);
    rD_attn<<<Bc * Hc * (Sc / 64), 256, smem>>>();

    rD_split<<<nb(M * Dc), 256>>>(attn, aoh, aol, M * Dc);
    rD_mmagemm<<<dim3(Dc / 128, M / 128), 256>>>(aoh, aol, woh, wol, out, M, Dc, Dc);
}